// round 10
// baseline (speedup 1.0000x reference)
#include <cuda_runtime.h>
#include <cstdint>

// Problem constants (fixed by setup_inputs)
#define BB 8
#define CC 256
#define HH 128
#define WW 96
#define HW (HH*WW)

// -------- scratch (device globals; no allocation allowed) --------
__device__ float g_corr[BB*49*HH*WW];   // lrelu(correlation)
__device__ float g_h1[BB*128*HH*WW];
__device__ float g_h2[BB*64*HH*WW];
__device__ float g_h3[BB*32*HH*WW];
__device__ float g_flow[BB*2*HH*WW];

__device__ __forceinline__ float lrelu_f(float v) { return v > 0.f ? v : 0.1f * v; }

// mma.sync m16n8k8 tf32, fp32 accumulate (raw f32 regs; HW uses tf32 bits)
__device__ __forceinline__ void mma_tf32(float* d, const uint32_t* a, const uint32_t* b) {
    asm volatile(
        "mma.sync.aligned.m16n8k8.row.col.f32.tf32.tf32.f32 "
        "{%0,%1,%2,%3}, {%4,%5,%6,%7}, {%8,%9}, {%0,%1,%2,%3};"
        : "+f"(d[0]), "+f"(d[1]), "+f"(d[2]), "+f"(d[3])
        : "r"(a[0]), "r"(a[1]), "r"(a[2]), "r"(a[3]),
          "r"(b[0]), "r"(b[1]));
}

// -------- cp.async helpers --------
__device__ __forceinline__ void cp_async4(uint32_t dst, const float* src, bool v) {
    asm volatile("cp.async.ca.shared.global [%0], [%1], 4, %2;"
                 :: "r"(dst), "l"(src), "r"(v ? 4u : 0u));
}
__device__ __forceinline__ void cp_commit() {
    asm volatile("cp.async.commit_group;");
}
template<int N> __device__ __forceinline__ void cp_wait() {
    asm volatile("cp.async.wait_group %0;" :: "n"(N));
}

// ============================================================================
// Correlation (unchanged from R5)
// ============================================================================
#define CKC 8
__global__ __launch_bounds__(384) void corr_kernel(
    const float* __restrict__ f1, const float* __restrict__ f2,
    float* __restrict__ out)
{
    const int tid = threadIdx.x;
    const int w   = tid % 96;
    const int r   = tid / 96;           // 0..3
    const int h0  = blockIdx.x * 4;
    const int b   = blockIdx.y;
    const int h   = h0 + r;

    __shared__ float s2[CKC][10][104];  // rows h0-3 .. h0+6, cols -3..98

    float acc[49];
#pragma unroll
    for (int i = 0; i < 49; ++i) acc[i] = 0.f;

    const float* f1p = f1 + ((size_t)b*CC*HH + h)*WW + w;

    for (int c0 = 0; c0 < CC; c0 += CKC) {
        __syncthreads();
        for (int idx = tid; idx < CKC*10*102; idx += 384) {
            int ci  = idx / 1020;
            int rem = idx - ci*1020;
            int rr  = rem / 102;
            int col = rem - rr*102;
            int gh = h0 + rr - 3;
            int gw = col - 3;
            float v = 0.f;
            if ((unsigned)gh < (unsigned)HH && (unsigned)gw < (unsigned)WW)
                v = f2[(((size_t)b*CC + c0 + ci)*HH + gh)*WW + gw];
            s2[ci][rr][col] = v;
        }
        __syncthreads();
#pragma unroll
        for (int ci = 0; ci < CKC; ++ci) {
            float a = f1p[(size_t)(c0 + ci)*HW];
#pragma unroll
            for (int dy = 0; dy < 7; ++dy) {
#pragma unroll
                for (int dx = 0; dx < 7; ++dx)
                    acc[dy*7 + dx] += a * s2[ci][r + dy][w + dx];
            }
        }
    }

#pragma unroll
    for (int o = 0; o < 49; ++o) {
        float t = acc[o] * (1.0f/256.0f);
        out[(((size_t)b*49 + o)*HH + h)*WW + w] = lrelu_f(t);
    }
}

// ============================================================================
// 3x3 conv — tf32 mma.sync implicit GEMM, cp.async double-buffered (CK=8),
// with k-pair-interleaved smem so every fragment pair is one LDS.64.
//
// s_in (floats): addr = g*456 + r*72 + col*2 + s   (ci = g + 4s, g=ci&3)
//   -> 8B units: g*228 + r*36 + col; 228%16==4 -> conflict-free B LDS.64.
// s_w  (floats): addr = g*584 + tap*64 + co*2 + s  (ci = g + 4s)
//   -> 8B units: g*292 + tap*32 + co; 292%16==4 -> conflict-free A LDS.64.
//
// Block = 128 thr (4 warps). Output tile: 32 couts x 4h x 32w.
// Per chunk per warp: 72 LDS.64 + 72 HMMA (was 144 LDS.32 + 72 HMMA).
// ============================================================================
template<int CIN, int COUT, bool RELU>
__global__ __launch_bounds__(128) void conv3x3_mma(
    const float* __restrict__ x, const float* __restrict__ wgt,
    const float* __restrict__ bias, float* __restrict__ y)
{
    constexpr int CK   = 8;
    constexpr int G_IN = 456;          // per-group float stride, input (228*2)
    constexpr int G_W  = 584;          // per-group float stride, weights (292*2)
    constexpr int NCH  = (CIN + CK - 1) / CK;

    __shared__ float s_in[2][4 * G_IN];   // 2 x 7296 B
    __shared__ float s_w [2][4 * G_W];    // 2 x 9344 B

    const int tid  = threadIdx.x;
    const int warp = tid >> 5;
    const int lane = tid & 31;

    const int w0 = blockIdx.x * 32;
    const int h0 = blockIdx.y * 4;
    constexpr int NCO = COUT / 32;
    const int co0 = (blockIdx.z % NCO) * 32;
    const int b   = blockIdx.z / NCO;

    float d[2][4][4];
#pragma unroll
    for (int m = 0; m < 2; ++m)
#pragma unroll
        for (int n = 0; n < 4; ++n)
#pragma unroll
            for (int k = 0; k < 4; ++k) d[m][n][k] = 0.f;

    // weight loader role: thread -> co = tid>>2, sub-lane j = tid&3
    const int l_co = tid >> 2;
    const int l_j  = tid & 3;
    const float* wbase = wgt + (size_t)(co0 + l_co)*CIN*9;

    auto issue = [&](int c0, int bf) {
        uint32_t sb_in = (uint32_t)__cvta_generic_to_shared(&s_in[bf][0]);
        uint32_t sb_w  = (uint32_t)__cvta_generic_to_shared(&s_w[bf][0]);
        // input tile: CK x 6 x 34 (rows h0-1..h0+4, cols w0-1..w0+32)
        for (int idx = tid; idx < CK*6*34; idx += 128) {
            int ci  = idx / 204;
            int rem = idx - ci*204;
            int rr  = rem / 34;
            int col = rem - rr*34;
            int gh = h0 + rr - 1;
            int gw = w0 + col - 1;
            bool v = (c0 + ci < CIN) &&
                     (unsigned)gh < (unsigned)HH && (unsigned)gw < (unsigned)WW;
            const float* src = v ?
                x + (((size_t)b*CIN + c0 + ci)*HH + gh)*WW + gw : x;
            uint32_t dstF = (uint32_t)((ci & 3)*G_IN + rr*72 + col*2 + (ci >> 2));
            cp_async4(sb_in + dstF*4u, src, v);
        }
        // weights: per thread its co; elems j, j+4, ... over ci*9+tap
        const float* wp = wbase + (size_t)c0*9;
#pragma unroll
        for (int e = l_j; e < CK*9; e += 4) {
            int ci  = e / 9;
            int tap = e - ci*9;
            bool v = (c0 + ci) < CIN;
            uint32_t dstF = (uint32_t)((ci & 3)*G_W + tap*64 + l_co*2 + (ci >> 2));
            cp_async4(sb_w + dstF*4u, v ? wp + e : wgt, v);
        }
    };

    issue(0, 0);
    cp_commit();

    int buf = 0;
    for (int ch = 0; ch < NCH; ++ch) {
        if (ch + 1 < NCH) {
            issue((ch + 1)*CK, buf ^ 1);
            cp_commit();
            cp_wait<1>();
        } else {
            cp_wait<0>();
        }
        __syncthreads();

        const uint2* si2 = (const uint2*)&s_in[buf][0];
        const uint2* sw2 = (const uint2*)&s_w[buf][0];

        const int gA = lane & 3;          // k group
        const int coA = lane >> 2;
        const int nB  = lane >> 2;

#pragma unroll
        for (int ky = 0; ky < 3; ++ky) {
#pragma unroll
            for (int kx = 0; kx < 3; ++kx) {
                const int tap = ky*3 + kx;
                // ---- A fragments: 4 x LDS.64 ----
                const int aoff = gA*292 + tap*32 + coA;  // 8B units
                uint2 aA = sw2[aoff     ];   // (co, k) , (co, k+4)
                uint2 aB = sw2[aoff +  8];   // co+8
                uint2 aC = sw2[aoff + 16];   // co+16 (m=1)
                uint2 aD = sw2[aoff + 24];   // co+24
                uint32_t a0[4] = { aA.x, aB.x, aA.y, aB.y };
                uint32_t a1[4] = { aC.x, aD.x, aC.y, aD.y };
                // ---- B fragments: 4 x LDS.64 + 8 MMA ----
                const int boff = gA*228 + (warp + ky)*36 + nB + kx;  // 8B units
#pragma unroll
                for (int nt = 0; nt < 4; ++nt) {
                    uint2 bv = si2[boff + nt*8];
                    uint32_t bf[2] = { bv.x, bv.y };
                    mma_tf32(d[0][nt], a0, bf);
                    mma_tf32(d[1][nt], a1, bf);
                }
            }
        }
        __syncthreads();
        buf ^= 1;
    }

    // ---- epilogue ----
#pragma unroll
    for (int m = 0; m < 2; ++m) {
        int co  = co0 + m*16 + (lane >> 2);
        float bv0 = bias[co];
        float bv1 = bias[co + 8];
        int h = h0 + warp;
#pragma unroll
        for (int nt = 0; nt < 4; ++nt) {
            int wc = w0 + nt*8 + (lane & 3)*2;
            float v0 = d[m][nt][0] + bv0;
            float v1 = d[m][nt][1] + bv0;
            float v2 = d[m][nt][2] + bv1;
            float v3 = d[m][nt][3] + bv1;
            if (RELU) {
                v0 = lrelu_f(v0); v1 = lrelu_f(v1);
                v2 = lrelu_f(v2); v3 = lrelu_f(v3);
            }
            float* yp = y + (((size_t)b*COUT + co)*HH + h)*WW + wc;
            yp[0]        = v0;
            yp[1]        = v1;
            yp[8*HW]     = v2;
            yp[8*HW + 1] = v3;
        }
    }
}

// ============================================================================
// Final 3x3 conv 32 -> 2 (flow). Unchanged.
// ============================================================================
__global__ __launch_bounds__(256) void conv_last_kernel(
    const float* __restrict__ x, const float* __restrict__ wgt,
    const float* __restrict__ bias, float* __restrict__ flow)
{
    __shared__ float sw[2*32*9];
    for (int i = threadIdx.x; i < 2*32*9; i += 256) sw[i] = wgt[i];
    __syncthreads();

    int idx = blockIdx.x*256 + threadIdx.x;
    int w = idx % WW;
    int h = (idx / WW) % HH;
    int b = idx / (WW*HH);

    float a0 = bias[0], a1 = bias[1];
    for (int ci = 0; ci < 32; ++ci) {
        const float* xp = x + ((size_t)(b*32 + ci))*HW;
        const float* w0p = &sw[(0*32 + ci)*9];
        const float* w1p = &sw[(1*32 + ci)*9];
#pragma unroll
        for (int ky = 0; ky < 3; ++ky) {
            int gh = h + ky - 1;
            if ((unsigned)gh >= (unsigned)HH) continue;
#pragma unroll
            for (int kx = 0; kx < 3; ++kx) {
                int gw = w + kx - 1;
                if ((unsigned)gw >= (unsigned)WW) continue;
                float v = xp[gh*WW + gw];
                a0 += v * w0p[ky*3 + kx];
                a1 += v * w1p[ky*3 + kx];
            }
        }
    }
    flow[((size_t)b*2*HH + h)*WW + w]        = a0;
    flow[(((size_t)b*2 + 1)*HH + h)*WW + w]  = a1;
}

// ============================================================================
// apply_offset + grid_sample fused — interpolation math hoisted out of the
// channel loop. Block = (h, b); 384 thr = 96 w x 4 c-slices of 64 channels.
// Per thread: indices/weights computed ONCE, then 64 iters of 4 LDG + FMA.
// ============================================================================
__global__ __launch_bounds__(384) void warp_kernel(
    const float* __restrict__ f2, const float* __restrict__ flow,
    float* __restrict__ out)
{
    const int tid = threadIdx.x;
    const int w   = tid % 96;
    const int cs  = tid / 96;            // 0..3 -> channels cs*64 .. cs*64+63
    const int h   = blockIdx.x;
    const int b   = blockIdx.y;

    float fx = flow[((size_t)b*2*HH + h)*WW + w];
    float fy = flow[(((size_t)b*2 + 1)*HH + h)*WW + w];

    float xx = fminf(fmaxf((float)w + fx, 0.f), (float)(WW-1));
    float yy = fminf(fmaxf((float)h + fy, 0.f), (float)(HH-1));
    float x0f = floorf(xx), y0f = floorf(yy);
    float wx = xx - x0f,  wy = yy - y0f;
    int x0 = (int)x0f, y0 = (int)y0f;
    int x1 = min(x0 + 1, WW-1);
    int y1 = min(y0 + 1, HH-1);

    const float w00 = (1.f-wx)*(1.f-wy);
    const float w01 = wx*(1.f-wy);
    const float w10 = (1.f-wx)*wy;
    const float w11 = wx*wy;

    const int i00 = y0*WW + x0;
    const int i01 = y0*WW + x1;
    const int i10 = y1*WW + x0;
    const int i11 = y1*WW + x1;

    const float* base = f2  + ((size_t)b*CC + cs*64)*HW;
    float*       op   = out + ((size_t)b*CC + cs*64)*HW + h*WW + w;

#pragma unroll 4
    for (int c = 0; c < 64; ++c) {
        const float* pp = base + (size_t)c*HW;
        float v = pp[i00]*w00 + pp[i01]*w01 + pp[i10]*w10 + pp[i11]*w11;
        op[(size_t)c*HW] = v;
    }
}

// ============================================================================
// launch
// ============================================================================
extern "C" void kernel_launch(void* const* d_in, const int* in_sizes, int n_in,
                              void* d_out, int out_size)
{
    const float* feat1 = (const float*)d_in[0];
    const float* feat2 = (const float*)d_in[1];
    const float* w1 = (const float*)d_in[2];
    const float* b1 = (const float*)d_in[3];
    const float* w2 = (const float*)d_in[4];
    const float* b2 = (const float*)d_in[5];
    const float* w3 = (const float*)d_in[6];
    const float* b3 = (const float*)d_in[7];
    const float* w4 = (const float*)d_in[8];
    const float* b4 = (const float*)d_in[9];
    float* out = (float*)d_out;

    float *p_corr, *p_h1, *p_h2, *p_h3, *p_flow;
    cudaGetSymbolAddress((void**)&p_corr, g_corr);
    cudaGetSymbolAddress((void**)&p_h1,   g_h1);
    cudaGetSymbolAddress((void**)&p_h2,   g_h2);
    cudaGetSymbolAddress((void**)&p_h3,   g_h3);
    cudaGetSymbolAddress((void**)&p_flow, g_flow);

    corr_kernel<<<dim3(HH/4, BB), 384>>>(feat1, feat2, p_corr);

    conv3x3_mma<49, 128, true><<<dim3(3, 32, BB*4), 128>>>(p_corr, w1, b1, p_h1);
    conv3x3_mma<128, 64, true><<<dim3(3, 32, BB*2), 128>>>(p_h1,  w2, b2, p_h2);
    conv3x3_mma<64,  32, true><<<dim3(3, 32, BB*1), 128>>>(p_h2,  w3, b3, p_h3);

    conv_last_kernel<<<(BB*HH*WW)/256, 256>>>(p_h3, w4, b4, p_flow);

    warp_kernel<<<dim3(HH, BB), 384>>>(feat2, p_flow, out);
}

// round 11
// speedup vs baseline: 1.4727x; 1.4727x over previous
#include <cuda_runtime.h>
#include <cstdint>

// Problem constants (fixed by setup_inputs)
#define BB 8
#define CC 256
#define HH 128
#define WW 96
#define HW (HH*WW)

// -------- scratch (device globals; no allocation allowed) --------
__device__ float g_corr[BB*49*HH*WW];   // lrelu(correlation)
__device__ float g_h1[BB*128*HH*WW];
__device__ float g_h2[BB*64*HH*WW];
__device__ float g_h3[BB*32*HH*WW];
__device__ float g_flow[BB*2*HH*WW];

__device__ __forceinline__ float lrelu_f(float v) { return v > 0.f ? v : 0.1f * v; }

// mma.sync m16n8k8 tf32, fp32 accumulate (raw f32 regs; HW uses tf32 bits)
__device__ __forceinline__ void mma_tf32(float* d, const uint32_t* a, const uint32_t* b) {
    asm volatile(
        "mma.sync.aligned.m16n8k8.row.col.f32.tf32.tf32.f32 "
        "{%0,%1,%2,%3}, {%4,%5,%6,%7}, {%8,%9}, {%0,%1,%2,%3};"
        : "+f"(d[0]), "+f"(d[1]), "+f"(d[2]), "+f"(d[3])
        : "r"(a[0]), "r"(a[1]), "r"(a[2]), "r"(a[3]),
          "r"(b[0]), "r"(b[1]));
}

// -------- cp.async helpers --------
__device__ __forceinline__ void cp_async4(uint32_t dst, const float* src, bool v) {
    asm volatile("cp.async.ca.shared.global [%0], [%1], 4, %2;"
                 :: "r"(dst), "l"(src), "r"(v ? 4u : 0u));
}
__device__ __forceinline__ void cp_commit() {
    asm volatile("cp.async.commit_group;");
}
template<int N> __device__ __forceinline__ void cp_wait() {
    asm volatile("cp.async.wait_group %0;" :: "n"(N));
}

// ============================================================================
// Correlation. Block = 384 thr = 4 output rows x 96 cols; window = 10 rows.
// Loader: cp.async with per-thread slot addressing hoisted out of the loop.
// ============================================================================
#define CKC 8
__global__ __launch_bounds__(384) void corr_kernel(
    const float* __restrict__ f1, const float* __restrict__ f2,
    float* __restrict__ out)
{
    const int tid = threadIdx.x;
    const int w   = tid % 96;
    const int r   = tid / 96;           // 0..3
    const int h0  = blockIdx.x * 4;
    const int b   = blockIdx.y;
    const int h   = h0 + r;

    __shared__ float s2[CKC*10*104];    // [ci][row 10][col 104]

    float acc[49];
#pragma unroll
    for (int i = 0; i < 49; ++i) acc[i] = 0.f;

    // ---- hoisted loader slots: elements j = tid + 384*s of a 10x102 tile ----
    int  rrS[3], dstS[3], goffS[3];
    bool inbS[3], haveS[3];
#pragma unroll
    for (int s = 0; s < 3; ++s) {
        int j = tid + 384*s;
        haveS[s] = j < 1020;
        int rr  = j / 102;
        int col = j - 102*rr;
        int gh  = h0 + rr - 3;
        int gw  = col - 3;
        inbS[s]  = (unsigned)gh < (unsigned)HH && (unsigned)gw < (unsigned)WW;
        goffS[s] = gh*WW + gw;
        dstS[s]  = rr*104 + col;
        rrS[s]   = rr;
    }
    const uint32_t sb = (uint32_t)__cvta_generic_to_shared(&s2[0]);
    const float* f1p = f1 + ((size_t)b*CC*HH + h)*WW + w;

    for (int c0 = 0; c0 < CC; c0 += CKC) {
        __syncthreads();
        const float* f2b = f2 + ((size_t)b*CC + c0)*HW;
#pragma unroll
        for (int ci = 0; ci < CKC; ++ci) {
#pragma unroll
            for (int s = 0; s < 3; ++s) {
                if (haveS[s]) {
                    bool v = inbS[s];
                    cp_async4(sb + (uint32_t)(ci*1040 + dstS[s])*4u,
                              v ? f2b + (size_t)ci*HW + goffS[s] : f2, v);
                }
            }
        }
        cp_commit();
        cp_wait<0>();
        __syncthreads();

#pragma unroll
        for (int ci = 0; ci < CKC; ++ci) {
            float a = f1p[(size_t)(c0 + ci)*HW];
            const float* s2c = &s2[ci*1040];
#pragma unroll
            for (int dy = 0; dy < 7; ++dy) {
                const float* row = s2c + (r + dy)*104 + w;
#pragma unroll
                for (int dx = 0; dx < 7; ++dx)
                    acc[dy*7 + dx] += a * row[dx];
            }
        }
    }

#pragma unroll
    for (int o = 0; o < 49; ++o) {
        float t = acc[o] * (1.0f/256.0f);
        out[(((size_t)b*49 + o)*HH + h)*WW + w] = lrelu_f(t);
    }
}

// ============================================================================
// 3x3 conv — tf32 mma.sync implicit GEMM, cp.async double-buffered (CK=8).
// R5 fragment scheme (LDS.32, conflict-free strides S=216, CIS=328).
// Loader addressing hoisted: per-thread slots computed once, reused per chunk.
// Block = 128 thr (4 warps). Output tile: 32 couts x 4h x 32w.
// ============================================================================
template<int CIN, int COUT, bool RELU>
__global__ __launch_bounds__(128) void conv3x3_mma(
    const float* __restrict__ x, const float* __restrict__ wgt,
    const float* __restrict__ bias, float* __restrict__ y)
{
    constexpr int CK  = 8;
    constexpr int R   = 36;            // row stride (floats)
    constexpr int S   = 6 * R;         // 216: ci stride in s_in
    constexpr int WS  = 36;            // tap stride in s_w
    constexpr int CIS = 9 * WS + 4;    // 328: ci stride in s_w
    constexpr int NCH = (CIN + CK - 1) / CK;

    __shared__ float s_in[2][CK * S];    // 2 x 6912 B
    __shared__ float s_w [2][CK * CIS];  // 2 x 10496 B

    const int tid  = threadIdx.x;
    const int warp = tid >> 5;
    const int lane = tid & 31;

    const int w0 = blockIdx.x * 32;
    const int h0 = blockIdx.y * 4;
    constexpr int NCO = COUT / 32;
    const int co0 = (blockIdx.z % NCO) * 32;
    const int b   = blockIdx.z / NCO;

    float d[2][4][4];
#pragma unroll
    for (int m = 0; m < 2; ++m)
#pragma unroll
        for (int n = 0; n < 4; ++n)
#pragma unroll
            for (int k = 0; k < 4; ++k) d[m][n][k] = 0.f;

    // ---- hoisted input-loader slots: elements j = tid + 128*s of 6x34 tile ----
    int  dstI[2], goffI[2];
    bool inbI[2], haveI[2];
#pragma unroll
    for (int s = 0; s < 2; ++s) {
        int j = tid + 128*s;
        haveI[s] = j < 204;
        int rr  = j / 34;
        int col = j - 34*rr;
        int gh  = h0 + rr - 1;
        int gw  = w0 + col - 1;
        inbI[s]  = (unsigned)gh < (unsigned)HH && (unsigned)gw < (unsigned)WW;
        goffI[s] = gh*WW + gw;
        dstI[s]  = rr*R + col;
    }

    // weight loader role: thread -> co = tid>>2, sub-lane j = tid&3
    const int l_co = tid >> 2;
    const int l_j  = tid & 3;
    const float* wbase = wgt + (size_t)(co0 + l_co)*CIN*9;

    auto issue = [&](int c0, int bf) {
        uint32_t sb_in = (uint32_t)__cvta_generic_to_shared(&s_in[bf][0]);
        uint32_t sb_w  = (uint32_t)__cvta_generic_to_shared(&s_w[bf][0]);
        const float* xb = x + ((size_t)b*CIN + c0)*HW;
        const float* wp = wbase + (size_t)c0*9;
#pragma unroll
        for (int ci = 0; ci < CK; ++ci) {
            bool cv = (c0 + ci) < CIN;
#pragma unroll
            for (int s = 0; s < 2; ++s) {
                if (haveI[s]) {
                    bool v = cv && inbI[s];
                    cp_async4(sb_in + (uint32_t)(ci*S + dstI[s])*4u,
                              v ? xb + (size_t)ci*HW + goffI[s] : x, v);
                }
            }
#pragma unroll
            for (int t = 0; t < 3; ++t) {
                int tap = l_j + 4*t;
                if (tap < 9)
                    cp_async4(sb_w + (uint32_t)(ci*CIS + tap*WS + l_co)*4u,
                              cv ? wp + ci*9 + tap : wgt, cv);
            }
        }
    };

    issue(0, 0);
    cp_commit();

    int buf = 0;
    for (int ch = 0; ch < NCH; ++ch) {
        if (ch + 1 < NCH) {
            issue((ch + 1)*CK, buf ^ 1);
            cp_commit();
            cp_wait<1>();
        } else {
            cp_wait<0>();
        }
        __syncthreads();

        const uint32_t* si  = (const uint32_t*)&s_in[buf][0];
        const uint32_t* swp = (const uint32_t*)&s_w[buf][0];

#pragma unroll
        for (int ky = 0; ky < 3; ++ky) {
#pragma unroll
            for (int kx = 0; kx < 3; ++kx) {
                const int tap = ky*3 + kx;
                // ---- A fragments (weights) ----
                const int ciA = lane & 3;
                const int coA = lane >> 2;
                uint32_t a[2][4];
#pragma unroll
                for (int m = 0; m < 2; ++m) {
                    int cob = m*16 + coA;
                    a[m][0] = swp[ ciA   *CIS + tap*WS + cob    ];
                    a[m][1] = swp[ ciA   *CIS + tap*WS + cob + 8];
                    a[m][2] = swp[(ciA+4)*CIS + tap*WS + cob    ];
                    a[m][3] = swp[(ciA+4)*CIS + tap*WS + cob + 8];
                }
                // ---- B fragments (input) ----
                const int rB  = warp + ky;
                const int ciB = lane & 3;
                const int nB  = lane >> 2;
                const uint32_t* bbase = si + ciB*S + rB*R + nB + kx;
#pragma unroll
                for (int nt = 0; nt < 4; ++nt) {
                    uint32_t bf[2];
                    bf[0] = bbase[nt*8];
                    bf[1] = bbase[nt*8 + 4*S];
                    mma_tf32(d[0][nt], a[0], bf);
                    mma_tf32(d[1][nt], a[1], bf);
                }
            }
        }
        __syncthreads();
        buf ^= 1;
    }

    // ---- epilogue (STG.64 pairs) ----
#pragma unroll
    for (int m = 0; m < 2; ++m) {
        int co  = co0 + m*16 + (lane >> 2);
        float bv0 = bias[co];
        float bv1 = bias[co + 8];
        int h = h0 + warp;
#pragma unroll
        for (int nt = 0; nt < 4; ++nt) {
            int wc = w0 + nt*8 + (lane & 3)*2;
            float v0 = d[m][nt][0] + bv0;
            float v1 = d[m][nt][1] + bv0;
            float v2 = d[m][nt][2] + bv1;
            float v3 = d[m][nt][3] + bv1;
            if (RELU) {
                v0 = lrelu_f(v0); v1 = lrelu_f(v1);
                v2 = lrelu_f(v2); v3 = lrelu_f(v3);
            }
            float* yp = y + (((size_t)b*COUT + co)*HH + h)*WW + wc;
            *reinterpret_cast<float2*>(yp)         = make_float2(v0, v1);
            *reinterpret_cast<float2*>(yp + 8*HW)  = make_float2(v2, v3);
        }
    }
}

// ============================================================================
// Final 3x3 conv 32 -> 2 (flow). Unchanged.
// ============================================================================
__global__ __launch_bounds__(256) void conv_last_kernel(
    const float* __restrict__ x, const float* __restrict__ wgt,
    const float* __restrict__ bias, float* __restrict__ flow)
{
    __shared__ float sw[2*32*9];
    for (int i = threadIdx.x; i < 2*32*9; i += 256) sw[i] = wgt[i];
    __syncthreads();

    int idx = blockIdx.x*256 + threadIdx.x;
    int w = idx % WW;
    int h = (idx / WW) % HH;
    int b = idx / (WW*HH);

    float a0 = bias[0], a1 = bias[1];
    for (int ci = 0; ci < 32; ++ci) {
        const float* xp = x + ((size_t)(b*32 + ci))*HW;
        const float* w0p = &sw[(0*32 + ci)*9];
        const float* w1p = &sw[(1*32 + ci)*9];
#pragma unroll
        for (int ky = 0; ky < 3; ++ky) {
            int gh = h + ky - 1;
            if ((unsigned)gh >= (unsigned)HH) continue;
#pragma unroll
            for (int kx = 0; kx < 3; ++kx) {
                int gw = w + kx - 1;
                if ((unsigned)gw >= (unsigned)WW) continue;
                float v = xp[gh*WW + gw];
                a0 += v * w0p[ky*3 + kx];
                a1 += v * w1p[ky*3 + kx];
            }
        }
    }
    flow[((size_t)b*2*HH + h)*WW + w]        = a0;
    flow[(((size_t)b*2 + 1)*HH + h)*WW + w]  = a1;
}

// ============================================================================
// apply_offset + grid_sample fused (R5 scheme: per-pixel math hoisted).
// ============================================================================
__global__ __launch_bounds__(384) void warp_kernel(
    const float* __restrict__ f2, const float* __restrict__ flow,
    float* __restrict__ out)
{
    const int tid = threadIdx.x;
    const int w   = tid % 96;
    const int cs  = tid / 96;            // 0..3 -> channels cs*64 .. cs*64+63
    const int h   = blockIdx.x;
    const int b   = blockIdx.y;

    float fx = flow[((size_t)b*2*HH + h)*WW + w];
    float fy = flow[(((size_t)b*2 + 1)*HH + h)*WW + w];

    float xx = fminf(fmaxf((float)w + fx, 0.f), (float)(WW-1));
    float yy = fminf(fmaxf((float)h + fy, 0.f), (float)(HH-1));
    float x0f = floorf(xx), y0f = floorf(yy);
    float wx = xx - x0f,  wy = yy - y0f;
    int x0 = (int)x0f, y0 = (int)y0f;
    int x1 = min(x0 + 1, WW-1);
    int y1 = min(y0 + 1, HH-1);

    const float w00 = (1.f-wx)*(1.f-wy);
    const float w01 = wx*(1.f-wy);
    const float w10 = (1.f-wx)*wy;
    const float w11 = wx*wy;

    const int i00 = y0*WW + x0;
    const int i01 = y0*WW + x1;
    const int i10 = y1*WW + x0;
    const int i11 = y1*WW + x1;

    const float* base = f2  + ((size_t)b*CC + cs*64)*HW;
    float*       op   = out + ((size_t)b*CC + cs*64)*HW + h*WW + w;

#pragma unroll 4
    for (int c = 0; c < 64; ++c) {
        const float* pp = base + (size_t)c*HW;
        float v = pp[i00]*w00 + pp[i01]*w01 + pp[i10]*w10 + pp[i11]*w11;
        op[(size_t)c*HW] = v;
    }
}

// ============================================================================
// launch
// ============================================================================
extern "C" void kernel_launch(void* const* d_in, const int* in_sizes, int n_in,
                              void* d_out, int out_size)
{
    const float* feat1 = (const float*)d_in[0];
    const float* feat2 = (const float*)d_in[1];
    const float* w1 = (const float*)d_in[2];
    const float* b1 = (const float*)d_in[3];
    const float* w2 = (const float*)d_in[4];
    const float* b2 = (const float*)d_in[5];
    const float* w3 = (const float*)d_in[6];
    const float* b3 = (const float*)d_in[7];
    const float* w4 = (const float*)d_in[8];
    const float* b4 = (const float*)d_in[9];
    float* out = (float*)d_out;

    float *p_corr, *p_h1, *p_h2, *p_h3, *p_flow;
    cudaGetSymbolAddress((void**)&p_corr, g_corr);
    cudaGetSymbolAddress((void**)&p_h1,   g_h1);
    cudaGetSymbolAddress((void**)&p_h2,   g_h2);
    cudaGetSymbolAddress((void**)&p_h3,   g_h3);
    cudaGetSymbolAddress((void**)&p_flow, g_flow);

    corr_kernel<<<dim3(HH/4, BB), 384>>>(feat1, feat2, p_corr);

    conv3x3_mma<49, 128, true><<<dim3(3, 32, BB*4), 128>>>(p_corr, w1, b1, p_h1);
    conv3x3_mma<128, 64, true><<<dim3(3, 32, BB*2), 128>>>(p_h1,  w2, b2, p_h2);
    conv3x3_mma<64,  32, true><<<dim3(3, 32, BB*1), 128>>>(p_h2,  w3, b3, p_h3);

    conv_last_kernel<<<(BB*HH*WW)/256, 256>>>(p_h3, w4, b4, p_flow);

    warp_kernel<<<dim3(HH, BB), 384>>>(feat2, p_flow, out);
}

// round 15
// speedup vs baseline: 1.6145x; 1.0963x over previous
#include <cuda_runtime.h>
#include <cstdint>

// Problem constants (fixed by setup_inputs)
#define BB 8
#define CC 256
#define HH 128
#define WW 96
#define HW (HH*WW)

// -------- scratch (device globals; no allocation allowed) --------
__device__ float g_corr[BB*49*HH*WW];   // lrelu(correlation)
__device__ float g_h1[BB*128*HH*WW];
__device__ float g_h2[BB*64*HH*WW];
__device__ float g_h3[BB*32*HH*WW];
__device__ float g_flow[BB*2*HH*WW];

__device__ __forceinline__ float lrelu_f(float v) { return v > 0.f ? v : 0.1f * v; }

// mma.sync m16n8k8 tf32, fp32 accumulate (raw f32 regs; HW uses tf32 bits)
__device__ __forceinline__ void mma_tf32(float* d, const uint32_t* a, const uint32_t* b) {
    asm volatile(
        "mma.sync.aligned.m16n8k8.row.col.f32.tf32.tf32.f32 "
        "{%0,%1,%2,%3}, {%4,%5,%6,%7}, {%8,%9}, {%0,%1,%2,%3};"
        : "+f"(d[0]), "+f"(d[1]), "+f"(d[2]), "+f"(d[3])
        : "r"(a[0]), "r"(a[1]), "r"(a[2]), "r"(a[3]),
          "r"(b[0]), "r"(b[1]));
}

// -------- cp.async helpers --------
__device__ __forceinline__ void cp_async4(uint32_t dst, const float* src, bool v) {
    asm volatile("cp.async.ca.shared.global [%0], [%1], 4, %2;"
                 :: "r"(dst), "l"(src), "r"(v ? 4u : 0u));
}
__device__ __forceinline__ void cp_commit() {
    asm volatile("cp.async.commit_group;");
}
template<int N> __device__ __forceinline__ void cp_wait() {
    asm volatile("cp.async.wait_group %0;" :: "n"(N));
}

// ============================================================================
// Correlation — 2 pixels per thread, LDS.64 row loads.
// Block = 192 thr = 4 rows x 48 pixel-pairs. Window = 10 rows x 112 (pad 3).
// Per ci per thread: 7 rows x 4 LDS.64 + 98 FMA (2 pixels x 49 disp).
// ============================================================================
#define CKC 8
__global__ __launch_bounds__(192) void corr_kernel(
    const float* __restrict__ f1, const float* __restrict__ f2,
    float* __restrict__ out)
{
    const int tid = threadIdx.x;
    const int t   = tid % 48;           // pixel pair -> pixels 2t, 2t+1
    const int r   = tid / 48;           // 0..3
    const int h0  = blockIdx.x * 4;
    const int b   = blockIdx.y;
    const int h   = h0 + r;

    __shared__ float s2[CKC*10*112];    // [ci][row 10][idx 112], idx = gw + 3

    float acc0[49], acc1[49];
#pragma unroll
    for (int i = 0; i < 49; ++i) { acc0[i] = 0.f; acc1[i] = 0.f; }

    // ---- hoisted loader slots: j = tid + 192*s over 10x102 tile ----
    int  dstS[6], goffS[6];
    bool inbS[6], haveS[6];
#pragma unroll
    for (int s = 0; s < 6; ++s) {
        int j = tid + 192*s;
        haveS[s] = j < 1020;
        int rr  = j / 102;
        int col = j - 102*rr;           // 0..101 -> idx col, gw = col-3
        int gh  = h0 + rr - 3;
        int gw  = col - 3;
        inbS[s]  = (unsigned)gh < (unsigned)HH && (unsigned)gw < (unsigned)WW;
        goffS[s] = gh*WW + gw;
        dstS[s]  = rr*112 + col;
    }
    const uint32_t sb = (uint32_t)__cvta_generic_to_shared(&s2[0]);
    const float* f1p = f1 + ((size_t)b*CC*HH + h)*WW + 2*t;

    for (int c0 = 0; c0 < CC; c0 += CKC) {
        __syncthreads();
        const float* f2b = f2 + ((size_t)b*CC + c0)*HW;
#pragma unroll
        for (int ci = 0; ci < CKC; ++ci) {
#pragma unroll
            for (int s = 0; s < 6; ++s) {
                if (haveS[s]) {
                    bool v = inbS[s];
                    cp_async4(sb + (uint32_t)(ci*1120 + dstS[s])*4u,
                              v ? f2b + (size_t)ci*HW + goffS[s] : f2, v);
                }
            }
        }
        cp_commit();
        cp_wait<0>();
        __syncthreads();

#pragma unroll
        for (int ci = 0; ci < CKC; ++ci) {
            float2 av = *reinterpret_cast<const float2*>(f1p + (size_t)(c0 + ci)*HW);
            const float* s2c = &s2[ci*1120];
#pragma unroll
            for (int dy = 0; dy < 7; ++dy) {
                // idx 2t .. 2t+7 == global cols 2t-3 .. 2t+4
                const float2* rp = reinterpret_cast<const float2*>(s2c + (r + dy)*112 + 2*t);
                float2 p0 = rp[0], p1 = rp[1], p2 = rp[2], p3 = rp[3];
                float rr_[8] = { p0.x, p0.y, p1.x, p1.y, p2.x, p2.y, p3.x, p3.y };
#pragma unroll
                for (int dx = 0; dx < 7; ++dx) {
                    acc0[dy*7 + dx] += av.x * rr_[dx];
                    acc1[dy*7 + dx] += av.y * rr_[dx + 1];
                }
            }
        }
    }

#pragma unroll
    for (int o = 0; o < 49; ++o) {
        float2 v;
        v.x = lrelu_f(acc0[o] * (1.0f/256.0f));
        v.y = lrelu_f(acc1[o] * (1.0f/256.0f));
        *reinterpret_cast<float2*>(out + (((size_t)b*49 + o)*HH + h)*WW + 2*t) = v;
    }
}

// ============================================================================
// 3x3 conv — tf32 mma.sync implicit GEMM, cp.async double-buffered (CK=8).
// 2 output rows per warp: block tile = 32 couts x 8h x 32w, 128 thr (4 warps).
// A fragments reused across both rows: per tap = 8 A-LDS + 16 B-LDS + 16 MMA.
// smem: s_in [ci][row 10][36]  S=360  (360%32==8  -> B frags conflict-free)
//       s_w  [ci][tap][co 32]  CIS=296 (296%32==8 -> A frags conflict-free)
// ============================================================================
template<int CIN, int COUT, bool RELU>
__global__ __launch_bounds__(128, 4) void conv3x3_mma(
    const float* __restrict__ x, const float* __restrict__ wgt,
    const float* __restrict__ bias, float* __restrict__ y)
{
    constexpr int CK  = 8;
    constexpr int R   = 36;             // row stride (floats)
    constexpr int S   = 10 * R;         // 360: ci stride in s_in
    constexpr int WS  = 32;             // tap stride in s_w
    constexpr int CIS = 9 * WS + 8;     // 296: ci stride in s_w
    constexpr int NCH = (CIN + CK - 1) / CK;

    __shared__ float s_in[2][CK * S];    // 2 x 11520 B
    __shared__ float s_w [2][CK * CIS];  // 2 x 9472 B

    const int tid  = threadIdx.x;
    const int warp = tid >> 5;
    const int lane = tid & 31;

    const int w0 = blockIdx.x * 32;
    const int h0 = blockIdx.y * 8;
    constexpr int NCO = COUT / 32;
    const int co0 = (blockIdx.z % NCO) * 32;
    const int b   = blockIdx.z / NCO;

    float d[2][2][4][4];                 // [m][row][nt][frag]
#pragma unroll
    for (int m = 0; m < 2; ++m)
#pragma unroll
        for (int rr2 = 0; rr2 < 2; ++rr2)
#pragma unroll
            for (int n = 0; n < 4; ++n)
#pragma unroll
                for (int k = 0; k < 4; ++k) d[m][rr2][n][k] = 0.f;

    // ---- hoisted input-loader slots: j = tid + 128*s over 10x34 tile ----
    int  dstI[3], goffI[3];
    bool inbI[3], haveI[3];
#pragma unroll
    for (int s = 0; s < 3; ++s) {
        int j = tid + 128*s;
        haveI[s] = j < 340;
        int rr  = j / 34;
        int col = j - 34*rr;
        int gh  = h0 + rr - 1;
        int gw  = w0 + col - 1;
        inbI[s]  = (unsigned)gh < (unsigned)HH && (unsigned)gw < (unsigned)WW;
        goffI[s] = gh*WW + gw;
        dstI[s]  = rr*R + col;
    }

    // weight loader role: thread -> co = tid>>2, sub-lane j = tid&3
    const int l_co = tid >> 2;
    const int l_j  = tid & 3;
    const float* wbase = wgt + (size_t)(co0 + l_co)*CIN*9;

    auto issue = [&](int c0, int bf) {
        uint32_t sb_in = (uint32_t)__cvta_generic_to_shared(&s_in[bf][0]);
        uint32_t sb_w  = (uint32_t)__cvta_generic_to_shared(&s_w[bf][0]);
        const float* xb = x + ((size_t)b*CIN + c0)*HW;
        const float* wp = wbase + (size_t)c0*9;
#pragma unroll
        for (int ci = 0; ci < CK; ++ci) {
            bool cv = (c0 + ci) < CIN;
#pragma unroll
            for (int s = 0; s < 3; ++s) {
                if (haveI[s]) {
                    bool v = cv && inbI[s];
                    cp_async4(sb_in + (uint32_t)(ci*S + dstI[s])*4u,
                              v ? xb + (size_t)ci*HW + goffI[s] : x, v);
                }
            }
#pragma unroll
            for (int t = 0; t < 3; ++t) {
                int tap = l_j + 4*t;
                if (tap < 9)
                    cp_async4(sb_w + (uint32_t)(ci*CIS + tap*WS + l_co)*4u,
                              cv ? wp + ci*9 + tap : wgt, cv);
            }
        }
    };

    issue(0, 0);
    cp_commit();

    int buf = 0;
    for (int ch = 0; ch < NCH; ++ch) {
        if (ch + 1 < NCH) {
            issue((ch + 1)*CK, buf ^ 1);
            cp_commit();
            cp_wait<1>();
        } else {
            cp_wait<0>();
        }
        __syncthreads();

        const uint32_t* si  = (const uint32_t*)&s_in[buf][0];
        const uint32_t* swp = (const uint32_t*)&s_w[buf][0];

        const int ciA = lane & 3;
        const int coA = lane >> 2;
        const int nB  = lane >> 2;

#pragma unroll
        for (int ky = 0; ky < 3; ++ky) {
#pragma unroll
            for (int kx = 0; kx < 3; ++kx) {
                const int tap = ky*3 + kx;
                // ---- A fragments (weights), shared by both rows ----
                uint32_t a[2][4];
#pragma unroll
                for (int m = 0; m < 2; ++m) {
                    int cob = m*16 + coA;
                    a[m][0] = swp[ ciA   *CIS + tap*WS + cob    ];
                    a[m][1] = swp[ ciA   *CIS + tap*WS + cob + 8];
                    a[m][2] = swp[(ciA+4)*CIS + tap*WS + cob    ];
                    a[m][3] = swp[(ciA+4)*CIS + tap*WS + cob + 8];
                }
                // ---- B fragments, 2 rows ----
#pragma unroll
                for (int rr2 = 0; rr2 < 2; ++rr2) {
                    const int row = 2*warp + rr2 + ky;
                    const uint32_t* bbase = si + ciA*S + row*R + nB + kx;
#pragma unroll
                    for (int nt = 0; nt < 4; ++nt) {
                        uint32_t bf[2];
                        bf[0] = bbase[nt*8];
                        bf[1] = bbase[nt*8 + 4*S];
                        mma_tf32(d[0][rr2][nt], a[0], bf);
                        mma_tf32(d[1][rr2][nt], a[1], bf);
                    }
                }
            }
        }
        __syncthreads();
        buf ^= 1;
    }

    // ---- epilogue (STG.64 pairs) ----
#pragma unroll
    for (int m = 0; m < 2; ++m) {
        int co  = co0 + m*16 + (lane >> 2);
        float bv0 = bias[co];
        float bv1 = bias[co + 8];
#pragma unroll
        for (int rr2 = 0; rr2 < 2; ++rr2) {
            int h = h0 + 2*warp + rr2;
#pragma unroll
            for (int nt = 0; nt < 4; ++nt) {
                int wc = w0 + nt*8 + (lane & 3)*2;
                float v0 = d[m][rr2][nt][0] + bv0;
                float v1 = d[m][rr2][nt][1] + bv0;
                float v2 = d[m][rr2][nt][2] + bv1;
                float v3 = d[m][rr2][nt][3] + bv1;
                if (RELU) {
                    v0 = lrelu_f(v0); v1 = lrelu_f(v1);
                    v2 = lrelu_f(v2); v3 = lrelu_f(v3);
                }
                float* yp = y + (((size_t)b*COUT + co)*HH + h)*WW + wc;
                *reinterpret_cast<float2*>(yp)        = make_float2(v0, v1);
                *reinterpret_cast<float2*>(yp + 8*HW) = make_float2(v2, v3);
            }
        }
    }
}

// ============================================================================
// Final 3x3 conv 32 -> 2 (flow). Unchanged.
// ============================================================================
__global__ __launch_bounds__(256) void conv_last_kernel(
    const float* __restrict__ x, const float* __restrict__ wgt,
    const float* __restrict__ bias, float* __restrict__ flow)
{
    __shared__ float sw[2*32*9];
    for (int i = threadIdx.x; i < 2*32*9; i += 256) sw[i] = wgt[i];
    __syncthreads();

    int idx = blockIdx.x*256 + threadIdx.x;
    int w = idx % WW;
    int h = (idx / WW) % HH;
    int b = idx / (WW*HH);

    float a0 = bias[0], a1 = bias[1];
    for (int ci = 0; ci < 32; ++ci) {
        const float* xp = x + ((size_t)(b*32 + ci))*HW;
        const float* w0p = &sw[(0*32 + ci)*9];
        const float* w1p = &sw[(1*32 + ci)*9];
#pragma unroll
        for (int ky = 0; ky < 3; ++ky) {
            int gh = h + ky - 1;
            if ((unsigned)gh >= (unsigned)HH) continue;
#pragma unroll
            for (int kx = 0; kx < 3; ++kx) {
                int gw = w + kx - 1;
                if ((unsigned)gw >= (unsigned)WW) continue;
                float v = xp[gh*WW + gw];
                a0 += v * w0p[ky*3 + kx];
                a1 += v * w1p[ky*3 + kx];
            }
        }
    }
    flow[((size_t)b*2*HH + h)*WW + w]        = a0;
    flow[(((size_t)b*2 + 1)*HH + h)*WW + w]  = a1;
}

// ============================================================================
// apply_offset + grid_sample fused (per-pixel math hoisted). Unchanged.
// ============================================================================
__global__ __launch_bounds__(384) void warp_kernel(
    const float* __restrict__ f2, const float* __restrict__ flow,
    float* __restrict__ out)
{
    const int tid = threadIdx.x;
    const int w   = tid % 96;
    const int cs  = tid / 96;            // 0..3 -> channels cs*64 .. cs*64+63
    const int h   = blockIdx.x;
    const int b   = blockIdx.y;

    float fx = flow[((size_t)b*2*HH + h)*WW + w];
    float fy = flow[(((size_t)b*2 + 1)*HH + h)*WW + w];

    float xx = fminf(fmaxf((float)w + fx, 0.f), (float)(WW-1));
    float yy = fminf(fmaxf((float)h + fy, 0.f), (float)(HH-1));
    float x0f = floorf(xx), y0f = floorf(yy);
    float wx = xx - x0f,  wy = yy - y0f;
    int x0 = (int)x0f, y0 = (int)y0f;
    int x1 = min(x0 + 1, WW-1);
    int y1 = min(y0 + 1, HH-1);

    const float w00 = (1.f-wx)*(1.f-wy);
    const float w01 = wx*(1.f-wy);
    const float w10 = (1.f-wx)*wy;
    const float w11 = wx*wy;

    const int i00 = y0*WW + x0;
    const int i01 = y0*WW + x1;
    const int i10 = y1*WW + x0;
    const int i11 = y1*WW + x1;

    const float* base = f2  + ((size_t)b*CC + cs*64)*HW;
    float*       op   = out + ((size_t)b*CC + cs*64)*HW + h*WW + w;

#pragma unroll 4
    for (int c = 0; c < 64; ++c) {
        const float* pp = base + (size_t)c*HW;
        float v = pp[i00]*w00 + pp[i01]*w01 + pp[i10]*w10 + pp[i11]*w11;
        op[(size_t)c*HW] = v;
    }
}

// ============================================================================
// launch
// ============================================================================
extern "C" void kernel_launch(void* const* d_in, const int* in_sizes, int n_in,
                              void* d_out, int out_size)
{
    const float* feat1 = (const float*)d_in[0];
    const float* feat2 = (const float*)d_in[1];
    const float* w1 = (const float*)d_in[2];
    const float* b1 = (const float*)d_in[3];
    const float* w2 = (const float*)d_in[4];
    const float* b2 = (const float*)d_in[5];
    const float* w3 = (const float*)d_in[6];
    const float* b3 = (const float*)d_in[7];
    const float* w4 = (const float*)d_in[8];
    const float* b4 = (const float*)d_in[9];
    float* out = (float*)d_out;

    float *p_corr, *p_h1, *p_h2, *p_h3, *p_flow;
    cudaGetSymbolAddress((void**)&p_corr, g_corr);
    cudaGetSymbolAddress((void**)&p_h1,   g_h1);
    cudaGetSymbolAddress((void**)&p_h2,   g_h2);
    cudaGetSymbolAddress((void**)&p_h3,   g_h3);
    cudaGetSymbolAddress((void**)&p_flow, g_flow);

    corr_kernel<<<dim3(HH/4, BB), 192>>>(feat1, feat2, p_corr);

    conv3x3_mma<49, 128, true><<<dim3(3, 16, BB*4), 128>>>(p_corr, w1, b1, p_h1);
    conv3x3_mma<128, 64, true><<<dim3(3, 16, BB*2), 128>>>(p_h1,  w2, b2, p_h2);
    conv3x3_mma<64,  32, true><<<dim3(3, 16, BB*1), 128>>>(p_h2,  w3, b3, p_h3);

    conv_last_kernel<<<(BB*HH*WW)/256, 256>>>(p_h3, w4, b4, p_flow);

    warp_kernel<<<dim3(HH, BB), 384>>>(feat2, p_flow, out);
}

// round 16
// speedup vs baseline: 1.8221x; 1.1286x over previous
#include <cuda_runtime.h>
#include <cstdint>

// Problem constants (fixed by setup_inputs)
#define BB 8
#define CC 256
#define HH 128
#define WW 96
#define HW (HH*WW)

// -------- scratch (device globals; no allocation allowed) --------
__device__ float g_corr[BB*49*HH*WW];   // lrelu(correlation)
__device__ float g_h1[BB*128*HH*WW];
__device__ float g_h2[BB*64*HH*WW];
__device__ float g_h3[BB*32*HH*WW];
__device__ float g_flow[BB*2*HH*WW];

__device__ __forceinline__ float lrelu_f(float v) { return v > 0.f ? v : 0.1f * v; }

// mma.sync m16n8k8 tf32, fp32 accumulate (raw f32 regs; HW uses tf32 bits)
__device__ __forceinline__ void mma_tf32(float* d, const uint32_t* a, const uint32_t* b) {
    asm volatile(
        "mma.sync.aligned.m16n8k8.row.col.f32.tf32.tf32.f32 "
        "{%0,%1,%2,%3}, {%4,%5,%6,%7}, {%8,%9}, {%0,%1,%2,%3};"
        : "+f"(d[0]), "+f"(d[1]), "+f"(d[2]), "+f"(d[3])
        : "r"(a[0]), "r"(a[1]), "r"(a[2]), "r"(a[3]),
          "r"(b[0]), "r"(b[1]));
}

// -------- cp.async helpers --------
__device__ __forceinline__ void cp_async4(uint32_t dst, const float* src, bool v) {
    asm volatile("cp.async.ca.shared.global [%0], [%1], 4, %2;"
                 :: "r"(dst), "l"(src), "r"(v ? 4u : 0u));
}
__device__ __forceinline__ void cp_commit() {
    asm volatile("cp.async.commit_group;");
}
template<int N> __device__ __forceinline__ void cp_wait() {
    asm volatile("cp.async.wait_group %0;" :: "n"(N));
}

// ============================================================================
// Correlation — 2 pixels per thread, LDS.64 row loads.
// Block = 192 thr = 4 rows x 48 pixel-pairs. Window = 10 rows x 112 (pad 3).
// NOW double-buffered over ci-chunks of 4 with single sync per chunk:
//   wait -> sync -> issue(next) -> compute.  Same smem footprint (2x17.9KB).
// ============================================================================
#define CKC 4
__global__ __launch_bounds__(192) void corr_kernel(
    const float* __restrict__ f1, const float* __restrict__ f2,
    float* __restrict__ out)
{
    const int tid = threadIdx.x;
    const int t   = tid % 48;           // pixel pair -> pixels 2t, 2t+1
    const int r   = tid / 48;           // 0..3
    const int h0  = blockIdx.x * 4;
    const int b   = blockIdx.y;
    const int h   = h0 + r;

    __shared__ float s2[2][CKC*10*112]; // [stage][ci][row 10][idx 112]

    float acc0[49], acc1[49];
#pragma unroll
    for (int i = 0; i < 49; ++i) { acc0[i] = 0.f; acc1[i] = 0.f; }

    // ---- hoisted loader slots: j = tid + 192*s over 10x102 tile (per ci) ----
    int  dstS[6], goffS[6];
    bool inbS[6], haveS[6];
#pragma unroll
    for (int s = 0; s < 6; ++s) {
        int j = tid + 192*s;
        haveS[s] = j < 1020;
        int rr  = j / 102;
        int col = j - 102*rr;           // 0..101 -> idx col, gw = col-3
        int gh  = h0 + rr - 3;
        int gw  = col - 3;
        inbS[s]  = (unsigned)gh < (unsigned)HH && (unsigned)gw < (unsigned)WW;
        goffS[s] = gh*WW + gw;
        dstS[s]  = rr*112 + col;
    }
    const float* f1p = f1 + ((size_t)b*CC*HH + h)*WW + 2*t;

    auto issue = [&](int c0, int bf) {
        const uint32_t sb = (uint32_t)__cvta_generic_to_shared(&s2[bf][0]);
        const float* f2b = f2 + ((size_t)b*CC + c0)*HW;
#pragma unroll
        for (int ci = 0; ci < CKC; ++ci) {
#pragma unroll
            for (int s = 0; s < 6; ++s) {
                if (haveS[s]) {
                    bool v = inbS[s];
                    cp_async4(sb + (uint32_t)(ci*1120 + dstS[s])*4u,
                              v ? f2b + (size_t)ci*HW + goffS[s] : f2, v);
                }
            }
        }
    };

    issue(0, 0);
    cp_commit();

    int buf = 0;
    for (int c0 = 0; c0 < CC; c0 += CKC) {
        cp_wait<0>();
        __syncthreads();
        if (c0 + CKC < CC) {
            issue(c0 + CKC, buf ^ 1);
            cp_commit();
        }
#pragma unroll
        for (int ci = 0; ci < CKC; ++ci) {
            float2 av = *reinterpret_cast<const float2*>(f1p + (size_t)(c0 + ci)*HW);
            const float* s2c = &s2[buf][ci*1120];
#pragma unroll
            for (int dy = 0; dy < 7; ++dy) {
                // idx 2t .. 2t+7 == global cols 2t-3 .. 2t+4
                const float2* rp = reinterpret_cast<const float2*>(s2c + (r + dy)*112 + 2*t);
                float2 p0 = rp[0], p1 = rp[1], p2 = rp[2], p3 = rp[3];
                float rr_[8] = { p0.x, p0.y, p1.x, p1.y, p2.x, p2.y, p3.x, p3.y };
#pragma unroll
                for (int dx = 0; dx < 7; ++dx) {
                    acc0[dy*7 + dx] += av.x * rr_[dx];
                    acc1[dy*7 + dx] += av.y * rr_[dx + 1];
                }
            }
        }
        buf ^= 1;
    }

#pragma unroll
    for (int o = 0; o < 49; ++o) {
        float2 v;
        v.x = lrelu_f(acc0[o] * (1.0f/256.0f));
        v.y = lrelu_f(acc1[o] * (1.0f/256.0f));
        *reinterpret_cast<float2*>(out + (((size_t)b*49 + o)*HH + h)*WW + 2*t) = v;
    }
}

// ============================================================================
// 3x3 conv — tf32 mma.sync implicit GEMM, cp.async double-buffered (CK=8).
// 2 output rows per warp: block tile = 32 couts x 8h x 32w, 128 thr (4 warps).
// Single sync per chunk: wait -> sync -> issue(next) -> compute.
// smem: s_in [ci][row 10][36]  S=360  (360%32==8  -> B frags conflict-free)
//       s_w  [ci][tap][co 32]  CIS=296 (296%32==8 -> A frags conflict-free)
// ============================================================================
template<int CIN, int COUT, bool RELU>
__global__ __launch_bounds__(128, 4) void conv3x3_mma(
    const float* __restrict__ x, const float* __restrict__ wgt,
    const float* __restrict__ bias, float* __restrict__ y)
{
    constexpr int CK  = 8;
    constexpr int R   = 36;             // row stride (floats)
    constexpr int S   = 10 * R;         // 360: ci stride in s_in
    constexpr int WS  = 32;             // tap stride in s_w
    constexpr int CIS = 9 * WS + 8;     // 296: ci stride in s_w
    constexpr int NCH = (CIN + CK - 1) / CK;

    __shared__ float s_in[2][CK * S];    // 2 x 11520 B
    __shared__ float s_w [2][CK * CIS];  // 2 x 9472 B

    const int tid  = threadIdx.x;
    const int warp = tid >> 5;
    const int lane = tid & 31;

    const int w0 = blockIdx.x * 32;
    const int h0 = blockIdx.y * 8;
    constexpr int NCO = COUT / 32;
    const int co0 = (blockIdx.z % NCO) * 32;
    const int b   = blockIdx.z / NCO;

    float d[2][2][4][4];                 // [m][row][nt][frag]
#pragma unroll
    for (int m = 0; m < 2; ++m)
#pragma unroll
        for (int rr2 = 0; rr2 < 2; ++rr2)
#pragma unroll
            for (int n = 0; n < 4; ++n)
#pragma unroll
                for (int k = 0; k < 4; ++k) d[m][rr2][n][k] = 0.f;

    // ---- hoisted input-loader slots: j = tid + 128*s over 10x34 tile ----
    int  dstI[3], goffI[3];
    bool inbI[3], haveI[3];
#pragma unroll
    for (int s = 0; s < 3; ++s) {
        int j = tid + 128*s;
        haveI[s] = j < 340;
        int rr  = j / 34;
        int col = j - 34*rr;
        int gh  = h0 + rr - 1;
        int gw  = w0 + col - 1;
        inbI[s]  = (unsigned)gh < (unsigned)HH && (unsigned)gw < (unsigned)WW;
        goffI[s] = gh*WW + gw;
        dstI[s]  = rr*R + col;
    }

    // weight loader role: thread -> co = tid>>2, sub-lane j = tid&3
    const int l_co = tid >> 2;
    const int l_j  = tid & 3;
    const float* wbase = wgt + (size_t)(co0 + l_co)*CIN*9;

    auto issue = [&](int c0, int bf) {
        uint32_t sb_in = (uint32_t)__cvta_generic_to_shared(&s_in[bf][0]);
        uint32_t sb_w  = (uint32_t)__cvta_generic_to_shared(&s_w[bf][0]);
        const float* xb = x + ((size_t)b*CIN + c0)*HW;
        const float* wp = wbase + (size_t)c0*9;
#pragma unroll
        for (int ci = 0; ci < CK; ++ci) {
            bool cv = (c0 + ci) < CIN;
#pragma unroll
            for (int s = 0; s < 3; ++s) {
                if (haveI[s]) {
                    bool v = cv && inbI[s];
                    cp_async4(sb_in + (uint32_t)(ci*S + dstI[s])*4u,
                              v ? xb + (size_t)ci*HW + goffI[s] : x, v);
                }
            }
#pragma unroll
            for (int t = 0; t < 3; ++t) {
                int tap = l_j + 4*t;
                if (tap < 9)
                    cp_async4(sb_w + (uint32_t)(ci*CIS + tap*WS + l_co)*4u,
                              cv ? wp + ci*9 + tap : wgt, cv);
            }
        }
    };

    issue(0, 0);
    cp_commit();

    int buf = 0;
    for (int ch = 0; ch < NCH; ++ch) {
        cp_wait<0>();
        __syncthreads();
        if (ch + 1 < NCH) {
            issue((ch + 1)*CK, buf ^ 1);
            cp_commit();
        }

        const uint32_t* si  = (const uint32_t*)&s_in[buf][0];
        const uint32_t* swp = (const uint32_t*)&s_w[buf][0];

        const int ciA = lane & 3;
        const int coA = lane >> 2;
        const int nB  = lane >> 2;

#pragma unroll
        for (int ky = 0; ky < 3; ++ky) {
#pragma unroll
            for (int kx = 0; kx < 3; ++kx) {
                const int tap = ky*3 + kx;
                // ---- A fragments (weights), shared by both rows ----
                uint32_t a[2][4];
#pragma unroll
                for (int m = 0; m < 2; ++m) {
                    int cob = m*16 + coA;
                    a[m][0] = swp[ ciA   *CIS + tap*WS + cob    ];
                    a[m][1] = swp[ ciA   *CIS + tap*WS + cob + 8];
                    a[m][2] = swp[(ciA+4)*CIS + tap*WS + cob    ];
                    a[m][3] = swp[(ciA+4)*CIS + tap*WS + cob + 8];
                }
                // ---- B fragments, 2 rows ----
#pragma unroll
                for (int rr2 = 0; rr2 < 2; ++rr2) {
                    const int row = 2*warp + rr2 + ky;
                    const uint32_t* bbase = si + ciA*S + row*R + nB + kx;
#pragma unroll
                    for (int nt = 0; nt < 4; ++nt) {
                        uint32_t bf[2];
                        bf[0] = bbase[nt*8];
                        bf[1] = bbase[nt*8 + 4*S];
                        mma_tf32(d[0][rr2][nt], a[0], bf);
                        mma_tf32(d[1][rr2][nt], a[1], bf);
                    }
                }
            }
        }
        buf ^= 1;
    }

    // ---- epilogue (STG.64 pairs) ----
#pragma unroll
    for (int m = 0; m < 2; ++m) {
        int co  = co0 + m*16 + (lane >> 2);
        float bv0 = bias[co];
        float bv1 = bias[co + 8];
#pragma unroll
        for (int rr2 = 0; rr2 < 2; ++rr2) {
            int h = h0 + 2*warp + rr2;
#pragma unroll
            for (int nt = 0; nt < 4; ++nt) {
                int wc = w0 + nt*8 + (lane & 3)*2;
                float v0 = d[m][rr2][nt][0] + bv0;
                float v1 = d[m][rr2][nt][1] + bv0;
                float v2 = d[m][rr2][nt][2] + bv1;
                float v3 = d[m][rr2][nt][3] + bv1;
                if (RELU) {
                    v0 = lrelu_f(v0); v1 = lrelu_f(v1);
                    v2 = lrelu_f(v2); v3 = lrelu_f(v3);
                }
                float* yp = y + (((size_t)b*COUT + co)*HH + h)*WW + wc;
                *reinterpret_cast<float2*>(yp)        = make_float2(v0, v1);
                *reinterpret_cast<float2*>(yp + 8*HW) = make_float2(v2, v3);
            }
        }
    }
}

// ============================================================================
// Final 3x3 conv 32 -> 2 (flow). Unchanged.
// ============================================================================
__global__ __launch_bounds__(256) void conv_last_kernel(
    const float* __restrict__ x, const float* __restrict__ wgt,
    const float* __restrict__ bias, float* __restrict__ flow)
{
    __shared__ float sw[2*32*9];
    for (int i = threadIdx.x; i < 2*32*9; i += 256) sw[i] = wgt[i];
    __syncthreads();

    int idx = blockIdx.x*256 + threadIdx.x;
    int w = idx % WW;
    int h = (idx / WW) % HH;
    int b = idx / (WW*HH);

    float a0 = bias[0], a1 = bias[1];
    for (int ci = 0; ci < 32; ++ci) {
        const float* xp = x + ((size_t)(b*32 + ci))*HW;
        const float* w0p = &sw[(0*32 + ci)*9];
        const float* w1p = &sw[(1*32 + ci)*9];
#pragma unroll
        for (int ky = 0; ky < 3; ++ky) {
            int gh = h + ky - 1;
            if ((unsigned)gh >= (unsigned)HH) continue;
#pragma unroll
            for (int kx = 0; kx < 3; ++kx) {
                int gw = w + kx - 1;
                if ((unsigned)gw >= (unsigned)WW) continue;
                float v = xp[gh*WW + gw];
                a0 += v * w0p[ky*3 + kx];
                a1 += v * w1p[ky*3 + kx];
            }
        }
    }
    flow[((size_t)b*2*HH + h)*WW + w]        = a0;
    flow[(((size_t)b*2 + 1)*HH + h)*WW + w]  = a1;
}

// ============================================================================
// apply_offset + grid_sample fused (per-pixel math hoisted). Unchanged.
// ============================================================================
__global__ __launch_bounds__(384) void warp_kernel(
    const float* __restrict__ f2, const float* __restrict__ flow,
    float* __restrict__ out)
{
    const int tid = threadIdx.x;
    const int w   = tid % 96;
    const int cs  = tid / 96;            // 0..3 -> channels cs*64 .. cs*64+63
    const int h   = blockIdx.x;
    const int b   = blockIdx.y;

    float fx = flow[((size_t)b*2*HH + h)*WW + w];
    float fy = flow[(((size_t)b*2 + 1)*HH + h)*WW + w];

    float xx = fminf(fmaxf((float)w + fx, 0.f), (float)(WW-1));
    float yy = fminf(fmaxf((float)h + fy, 0.f), (float)(HH-1));
    float x0f = floorf(xx), y0f = floorf(yy);
    float wx = xx - x0f,  wy = yy - y0f;
    int x0 = (int)x0f, y0 = (int)y0f;
    int x1 = min(x0 + 1, WW-1);
    int y1 = min(y0 + 1, HH-1);

    const float w00 = (1.f-wx)*(1.f-wy);
    const float w01 = wx*(1.f-wy);
    const float w10 = (1.f-wx)*wy;
    const float w11 = wx*wy;

    const int i00 = y0*WW + x0;
    const int i01 = y0*WW + x1;
    const int i10 = y1*WW + x0;
    const int i11 = y1*WW + x1;

    const float* base = f2  + ((size_t)b*CC + cs*64)*HW;
    float*       op   = out + ((size_t)b*CC + cs*64)*HW + h*WW + w;

#pragma unroll 4
    for (int c = 0; c < 64; ++c) {
        const float* pp = base + (size_t)c*HW;
        float v = pp[i00]*w00 + pp[i01]*w01 + pp[i10]*w10 + pp[i11]*w11;
        op[(size_t)c*HW] = v;
    }
}

// ============================================================================
// launch
// ============================================================================
extern "C" void kernel_launch(void* const* d_in, const int* in_sizes, int n_in,
                              void* d_out, int out_size)
{
    const float* feat1 = (const float*)d_in[0];
    const float* feat2 = (const float*)d_in[1];
    const float* w1 = (const float*)d_in[2];
    const float* b1 = (const float*)d_in[3];
    const float* w2 = (const float*)d_in[4];
    const float* b2 = (const float*)d_in[5];
    const float* w3 = (const float*)d_in[6];
    const float* b3 = (const float*)d_in[7];
    const float* w4 = (const float*)d_in[8];
    const float* b4 = (const float*)d_in[9];
    float* out = (float*)d_out;

    float *p_corr, *p_h1, *p_h2, *p_h3, *p_flow;
    cudaGetSymbolAddress((void**)&p_corr, g_corr);
    cudaGetSymbolAddress((void**)&p_h1,   g_h1);
    cudaGetSymbolAddress((void**)&p_h2,   g_h2);
    cudaGetSymbolAddress((void**)&p_h3,   g_h3);
    cudaGetSymbolAddress((void**)&p_flow, g_flow);

    corr_kernel<<<dim3(HH/4, BB), 192>>>(feat1, feat2, p_corr);

    conv3x3_mma<49, 128, true><<<dim3(3, 16, BB*4), 128>>>(p_corr, w1, b1, p_h1);
    conv3x3_mma<128, 64, true><<<dim3(3, 16, BB*2), 128>>>(p_h1,  w2, b2, p_h2);
    conv3x3_mma<64,  32, true><<<dim3(3, 16, BB*1), 128>>>(p_h2,  w3, b3, p_h3);

    conv_last_kernel<<<(BB*HH*WW)/256, 256>>>(p_h3, w4, b4, p_flow);

    warp_kernel<<<dim3(HH, BB), 384>>>(feat2, p_flow, out);
}